// round 13
// baseline (speedup 1.0000x reference)
#include <cuda_runtime.h>
#include <cstdint>

// Embedding gather + sinusoidal positional encoding.
// out[row, c] = W[ids[row], c] + (row even ? sin : cos)(row * freq(c)),
//   freq(c) = 10000^(-2c/D)
//
// D = 1024, TOKENS = 8192. Grid = 1024 CTAs x 8 rows, 256 threads.
// Thread t < 128  -> even rows r0+{0,2,4,6} (sin), cols 8*t   .. 8*t+7
// Thread t >= 128 -> odd  rows r0+{1,3,5,7} (cos), cols 8*(t-128) ..
// Gathers use sm_103a 256-bit loads (ld.global.nc.v8.b32): 4 LDG.256 per
// thread front-batched = 128 B in flight per thread (~2x bytes/reg vs .128).
// PE per column: one seed sincos + one delta(2f) sincos, then rows +2/+4/+6
// via double-angle / angle-addition identities (pure FMA, no serial chain).

static constexpr int D       = 1024;
static constexpr int VEC     = 8;
static constexpr int THREADS = 256;
static constexpr int R       = 8;          // rows per CTA

// sincos for 0 <= x <= ~8200: 3-term Cody-Waite reduction mod 2*pi, then MUFU.
__device__ __forceinline__ void fast_sincos(float x, float& s, float& c)
{
    const float INV2PI = 0.15915494309189535f;
    const float C1 = 6.28125f;
    const float C2 = 1.93530717957e-3f;
    const float C3 = 6.1232339957e-10f;
    float q = rintf(x * INV2PI);
    float a = fmaf(-q, C1, x);
    a = fmaf(-q, C2, a);
    a = fmaf(-q, C3, a);
    s = __sinf(a);
    c = __cosf(a);
}

// 256-bit non-coherent gather load (sm_100+).
__device__ __forceinline__ void ldg256(const float* p, float* v)
{
    uint32_t r0, r1, r2, r3, r4, r5, r6, r7;
    asm("ld.global.nc.v8.b32 {%0,%1,%2,%3,%4,%5,%6,%7}, [%8];"
        : "=r"(r0), "=r"(r1), "=r"(r2), "=r"(r3),
          "=r"(r4), "=r"(r5), "=r"(r6), "=r"(r7)
        : "l"(p));
    v[0] = __uint_as_float(r0); v[1] = __uint_as_float(r1);
    v[2] = __uint_as_float(r2); v[3] = __uint_as_float(r3);
    v[4] = __uint_as_float(r4); v[5] = __uint_as_float(r5);
    v[6] = __uint_as_float(r6); v[7] = __uint_as_float(r7);
}

__global__ __launch_bounds__(THREADS, 5)
void emb_pe_kernel(const int* __restrict__ ids,
                   const float* __restrict__ W,
                   float* __restrict__ out)
{
    const int row0 = blockIdx.x * R;            // multiple of 8 -> even
    const int t    = threadIdx.x;               // 0..255
    const int pair = t >> 7;                    // 0: even rows (sin), 1: odd (cos)
    const int c0   = (t & 127) * VEC;           // starting column (32B aligned)

    // This thread's 4 row ids: rows r0 + pair + {0,2,4,6}.
    const int4 iiA = *reinterpret_cast<const int4*>(ids + row0);      // rows 0..3
    const int4 iiB = *reinterpret_cast<const int4*>(ids + row0 + 4);  // rows 4..7
    int id[4];
    if (pair == 0) { id[0] = iiA.x; id[1] = iiA.z; id[2] = iiB.x; id[3] = iiB.z; }
    else           { id[0] = iiA.y; id[1] = iiA.w; id[2] = iiB.y; id[3] = iiB.w; }

    const float* Wc = W + c0;

    // Front-batch 4 x LDG.256 (128 B in flight per thread).
    float v[4][VEC];
#pragma unroll
    for (int k = 0; k < 4; k++)
        ldg256(Wc + (size_t)id[k] * D, v[k]);

    // PE (overlaps gather latency).
    // freq(c) = 2^(kexp * c),  kexp = -2*log2(10000)/D
    const float kexp = -13.287712379549449f * 2.0f / (float)D;
    const float pos  = (float)(row0 + pair);    // this thread's first row

#pragma unroll
    for (int i = 0; i < VEC; i++) {
        float freq = exp2f(kexp * (float)(c0 + i));
        float s, c, s2, c2;
        fast_sincos(pos * freq, s, c);          // seed at first row
        fast_sincos(2.0f * freq, s2, c2);       // +2 rows delta
        // +4 rows (double of 2d), +6 rows (4d + 2d): pure FMA.
        float s4 = 2.0f * s2 * c2;
        float c4 = fmaf(-2.0f * s2, s2, 1.0f);
        float s6 = fmaf(s4, c2,  c4 * s2);
        float c6 = fmaf(c4, c2, -s4 * s2);

        if (pair == 0) {                        // even rows: sin(a + k*2d)
            v[0][i] += s;
            v[1][i] += fmaf(s, c2,  c * s2);
            v[2][i] += fmaf(s, c4,  c * s4);
            v[3][i] += fmaf(s, c6,  c * s6);
        } else {                                // odd rows: cos(a + k*2d)
            v[0][i] += c;
            v[1][i] += fmaf(c, c2, -s * s2);
            v[2][i] += fmaf(c, c4, -s * s4);
            v[3][i] += fmaf(c, c6, -s * s6);
        }
    }

    // Stores: 4 rows x 32 B (two STG.128 each).
    float* outp = out + (size_t)(row0 + pair) * D + c0;
#pragma unroll
    for (int k = 0; k < 4; k++) {
        float4 a, b;
        a.x = v[k][0]; a.y = v[k][1]; a.z = v[k][2]; a.w = v[k][3];
        b.x = v[k][4]; b.y = v[k][5]; b.z = v[k][6]; b.w = v[k][7];
        float* p = outp + (size_t)(2 * k) * D;
        *reinterpret_cast<float4*>(p)     = a;
        *reinterpret_cast<float4*>(p + 4) = b;
    }
}

extern "C" void kernel_launch(void* const* d_in, const int* in_sizes, int n_in,
                              void* d_out, int out_size)
{
    const int*   ids = (const int*)d_in[0];
    const float* W   = (const float*)d_in[1];
    float*       out = (float*)d_out;

    const int rows = in_sizes[0];               // 8192 tokens
    emb_pe_kernel<<<rows / R, THREADS>>>(ids, W, out);
}

// round 14
// speedup vs baseline: 1.4681x; 1.4681x over previous
#include <cuda_runtime.h>
#include <cstdint>

// Embedding gather + sinusoidal positional encoding.
// out[row, c] = W[ids[row], c] + (row even ? sin : cos)(row * freq(c)),
//   freq(c) = 10000^(-2c/D)
//
// D = 1024, TOKENS = 8192. Grid = 1024 CTAs x 8 rows, 256 threads,
// __launch_bounds__(256, 6) -> 6 CTAs/SM -> n_conc = 888 -> ~1.15 waves
// (vs 2.3 waves for the grid=2048 shapes). Rows processed in two 4-row
// phases that REUSE the same value registers (keeps regs <= 40), each phase
// front-batching 4 independent LDG.128 (MLP=4). One ids load (2x int4)
// amortized over all 8 rows. PE per phase: one seed sincos + one delta
// sincos, remaining rows via double/triple-angle identities (pure FMA).

static constexpr int D       = 1024;
static constexpr int VEC     = 4;
static constexpr int THREADS = D / VEC;   // 256
static constexpr int R       = 8;         // rows per CTA

// sincos for 0 <= x <= ~8200: 3-term Cody-Waite reduction mod 2*pi, then MUFU.
__device__ __forceinline__ void fast_sincos(float x, float& s, float& c)
{
    const float INV2PI = 0.15915494309189535f;
    const float C1 = 6.28125f;
    const float C2 = 1.93530717957e-3f;
    const float C3 = 6.1232339957e-10f;
    float q = rintf(x * INV2PI);
    float a = fmaf(-q, C1, x);
    a = fmaf(-q, C2, a);
    a = fmaf(-q, C3, a);
    s = __sinf(a);
    c = __cosf(a);
}

// One 4-row phase: gather 4 rows (front-batched), add PE (rows p0..p0+3,
// p0 even -> sin/cos/sin/cos), store.
__device__ __forceinline__ void do_phase(const float* __restrict__ Wc,
                                         float* __restrict__ outp,
                                         const int* id, int p0, int c0,
                                         float kexp)
{
    // Front-batch 4 independent LDG.128.
    float4 v0 = *reinterpret_cast<const float4*>(Wc + (size_t)id[0] * D);
    float4 v1 = *reinterpret_cast<const float4*>(Wc + (size_t)id[1] * D);
    float4 v2 = *reinterpret_cast<const float4*>(Wc + (size_t)id[2] * D);
    float4 v3 = *reinterpret_cast<const float4*>(Wc + (size_t)id[3] * D);

    const float pos0 = (float)p0;
    float* p0v = &v0.x;
    float* p1v = &v1.x;
    float* p2v = &v2.x;
    float* p3v = &v3.x;

#pragma unroll
    for (int i = 0; i < VEC; i++) {
        float freq = exp2f(kexp * (float)(c0 + i));
        float s0, cc0, sd, cd;
        fast_sincos(pos0 * freq, s0, cc0);    // seed at row p0 (even)
        fast_sincos(freq,        sd, cd);     // +1 row delta
        float s2d = 2.0f * sd * cd;           // double angle
        float c2d = fmaf(-2.0f * sd, sd, 1.0f);
        float s3d = fmaf(s2d, cd,  c2d * sd); // triple angle
        float c3d = fmaf(c2d, cd, -s2d * sd);
        p0v[i] += s0;                          // sin(p0 f)
        p1v[i] += fmaf(cc0, cd, -s0 * sd);     // cos((p0+1) f)
        p2v[i] += fmaf(s0, c2d,  cc0 * s2d);   // sin((p0+2) f)
        p3v[i] += fmaf(cc0, c3d, -s0 * s3d);   // cos((p0+3) f)
    }

    *reinterpret_cast<float4*>(outp)         = v0;
    *reinterpret_cast<float4*>(outp + D)     = v1;
    *reinterpret_cast<float4*>(outp + 2 * D) = v2;
    *reinterpret_cast<float4*>(outp + 3 * D) = v3;
}

__global__ __launch_bounds__(THREADS, 6)
void emb_pe_kernel(const int* __restrict__ ids,
                   const float* __restrict__ W,
                   float* __restrict__ out)
{
    const int row0 = blockIdx.x * R;          // multiple of 8 -> even
    const int t    = threadIdx.x;             // 0..255
    const int c0   = t * VEC;                 // starting column

    // This CTA's 8 ids (two aligned int4 loads, amortized over 8 rows).
    const int4 iiA = *reinterpret_cast<const int4*>(ids + row0);
    const int4 iiB = *reinterpret_cast<const int4*>(ids + row0 + 4);
    int idA[4] = { iiA.x, iiA.y, iiA.z, iiA.w };
    int idB[4] = { iiB.x, iiB.y, iiB.z, iiB.w };

    const float kexp = -13.287712379549449f * 2.0f / (float)D;
    const float* Wc  = W + c0;
    float* outp      = out + (size_t)row0 * D + c0;

    do_phase(Wc, outp,         idA, row0,     c0, kexp);
    do_phase(Wc, outp + 4 * D, idB, row0 + 4, c0, kexp);
}

extern "C" void kernel_launch(void* const* d_in, const int* in_sizes, int n_in,
                              void* d_out, int out_size)
{
    const int*   ids = (const int*)d_in[0];
    const float* W   = (const float*)d_in[1];
    float*       out = (float*)d_out;

    const int rows = in_sizes[0];             // 8192 tokens
    emb_pe_kernel<<<rows / R, THREADS>>>(ids, W, out);
}

// round 15
// speedup vs baseline: 1.7515x; 1.1930x over previous
#include <cuda_runtime.h>
#include <cuda_bf16.h>
#include <cstdint>

// Embedding gather + sinusoidal positional encoding — FINAL (R7 config).
// out[row, c] = W[ids[row], c] + (row even ? sin : cos)(row * freq(c)),
//   freq(c) = 10000^(-2c/D)
//
// D = 1024, TOKENS = 8192. Grid = 2048 CTAs x 4 rows, 256 threads.
// Best-measured configuration across 14 rounds (bench 10.72 us, reproduced
// 3x): front-batched LDG.128 gathers (MLP=4), single int4 ids load,
// Cody-Waite reduction + MUFU __sinf/__cosf prologue, rotor recurrence for
// the 4 per-row PE values. All perturbations (cache hints, cp.async, angle
// flattening, higher occupancy, 256-bit loads, persistent grids, phase
// reuse) measured equal or worse — this is the structural floor set by
// per-CTA dependent-gather latency + launch overhead + compulsory 32 MB
// write drain, with no pipe above ~37%.

static constexpr int D       = 1024;
static constexpr int VEC     = 4;
static constexpr int THREADS = D / VEC;   // 256
static constexpr int R       = 4;         // rows per block (multiple of 2)

// sincos for 0 <= x <= ~8200: 3-term Cody-Waite reduction mod 2*pi, then MUFU.
__device__ __forceinline__ void fast_sincos(float x, float& s, float& c)
{
    const float INV2PI = 0.15915494309189535f;
    const float C1 = 6.28125f;
    const float C2 = 1.93530717957e-3f;
    const float C3 = 6.1232339957e-10f;
    float q = rintf(x * INV2PI);
    float a = fmaf(-q, C1, x);
    a = fmaf(-q, C2, a);
    a = fmaf(-q, C3, a);
    s = __sinf(a);
    c = __cosf(a);
}

__global__ __launch_bounds__(THREADS, 6)
void emb_pe_kernel(const int* __restrict__ ids,
                   const float* __restrict__ W,
                   float* __restrict__ out)
{
    const int row0 = blockIdx.x * R;          // multiple of 4 -> even
    const int t    = threadIdx.x;             // 0..255
    const int c0   = t * VEC;                 // starting column

    // One 16B load covers this CTA's 4 ids (aligned since row0 % 4 == 0).
    const int4 ii = *reinterpret_cast<const int4*>(ids + row0);

    const float* Wc = W + c0;

    // Front-batch all 4 gathers (independent LDG.128, MLP=4).
    const float4 v0 = *reinterpret_cast<const float4*>(Wc + (size_t)ii.x * D);
    const float4 v1 = *reinterpret_cast<const float4*>(Wc + (size_t)ii.y * D);
    const float4 v2 = *reinterpret_cast<const float4*>(Wc + (size_t)ii.z * D);
    const float4 v3 = *reinterpret_cast<const float4*>(Wc + (size_t)ii.w * D);

    // freq(c) = 2^(kexp * c),  kexp = -2*log2(10000)/D  (overlaps load latency)
    const float kexp = -13.287712379549449f * 2.0f / (float)D;
    const float pos0 = (float)row0;

    float s[VEC], c[VEC], sd[VEC], cd[VEC];
#pragma unroll
    for (int i = 0; i < VEC; i++) {
        float freq = exp2f(kexp * (float)(c0 + i));
        fast_sincos(pos0 * freq, s[i], c[i]);   // start rotor
        fast_sincos(freq,        sd[i], cd[i]); // +1 row delta rotor
    }

    float* outp = out + (size_t)row0 * D + c0;
    float4 o;

    // row0 (even): + sin
    o.x = v0.x + s[0]; o.y = v0.y + s[1]; o.z = v0.z + s[2]; o.w = v0.w + s[3];
    *reinterpret_cast<float4*>(outp) = o;

#pragma unroll
    for (int i = 0; i < VEC; i++) {           // rotate +1
        float ns = fmaf(s[i], cd[i],  c[i] * sd[i]);
        float nc = fmaf(c[i], cd[i], -s[i] * sd[i]);
        s[i] = ns; c[i] = nc;
    }

    // row0+1 (odd): + cos
    o.x = v1.x + c[0]; o.y = v1.y + c[1]; o.z = v1.z + c[2]; o.w = v1.w + c[3];
    *reinterpret_cast<float4*>(outp + D) = o;

#pragma unroll
    for (int i = 0; i < VEC; i++) {           // rotate +1
        float ns = fmaf(s[i], cd[i],  c[i] * sd[i]);
        float nc = fmaf(c[i], cd[i], -s[i] * sd[i]);
        s[i] = ns; c[i] = nc;
    }

    // row0+2 (even): + sin
    o.x = v2.x + s[0]; o.y = v2.y + s[1]; o.z = v2.z + s[2]; o.w = v2.w + s[3];
    *reinterpret_cast<float4*>(outp + 2 * D) = o;

#pragma unroll
    for (int i = 0; i < VEC; i++) {           // rotate +1
        float ns = fmaf(s[i], cd[i],  c[i] * sd[i]);
        float nc = fmaf(c[i], cd[i], -s[i] * sd[i]);
        s[i] = ns; c[i] = nc;
    }

    // row0+3 (odd): + cos
    o.x = v3.x + c[0]; o.y = v3.y + c[1]; o.z = v3.z + c[2]; o.w = v3.w + c[3];
    *reinterpret_cast<float4*>(outp + 3 * D) = o;
}

extern "C" void kernel_launch(void* const* d_in, const int* in_sizes, int n_in,
                              void* d_out, int out_size)
{
    const int*   ids = (const int*)d_in[0];
    const float* W   = (const float*)d_in[1];
    float*       out = (float*)d_out;

    const int rows = in_sizes[0];             // 8192 tokens
    emb_pe_kernel<<<rows / R, THREADS>>>(ids, W, out);
}